// round 13
// baseline (speedup 1.0000x reference)
#include <cuda_runtime.h>
#include <cuda_bf16.h>
#include <cstdint>
#include <cstddef>

#define DM 19
#define HID 512
#define NH 8
#define DH 64
#define BB 16
#define LL 1024
#define NTOK (BB*LL)
#define MQ 32

#define OUT_ELEMS   (NTOK*DM)
#define ATTN_ELEMS  ((size_t)BB*NH*LL*LL)

// ---- scratch ----
__device__ __align__(256) __nv_bfloat16 g_qs[(size_t)BB*NH*LL*128];  // [bh][l][hi64|lo64]
__device__ __align__(256) __nv_bfloat16 g_ks[(size_t)BB*NH*LL*128];
__device__ __align__(256) float         g_v [(size_t)BB*NH*LL*DH];
__device__ __align__(256) __nv_bfloat16 g_vT[(size_t)BB*NH*DH*LL];   // [bh][d][l]
__device__ __align__(256) float         g_ctx[(size_t)NTOK*HID];

// ---- helpers ----
__device__ __forceinline__ uint32_t s2u(const void* p) {
    uint32_t a;
    asm("{ .reg .u64 t; cvta.to.shared.u64 t, %1; cvt.u32.u64 %0, t; }" : "=r"(a) : "l"(p));
    return a;
}
__device__ __forceinline__ void cp16(uint32_t dst, const void* src) {
    asm volatile("cp.async.cg.shared.global [%0], [%1], 16;"
                 :: "r"(dst), "l"(__cvta_generic_to_global(src)));
}
#define CP_COMMIT() asm volatile("cp.async.commit_group;" ::: "memory")
#define CP_WAIT(n)  asm volatile("cp.async.wait_group %0;" :: "n"(n) : "memory")

#define MMA16816(c, a0, a1, a2, a3, b0, b1)                                   \
    asm volatile("mma.sync.aligned.m16n8k16.row.col.f32.bf16.bf16.f32 "       \
        "{%0,%1,%2,%3}, {%4,%5,%6,%7}, {%8,%9}, {%0,%1,%2,%3};"               \
        : "+f"((c)[0]), "+f"((c)[1]), "+f"((c)[2]), "+f"((c)[3])              \
        : "r"(a0), "r"(a1), "r"(a2), "r"(a3), "r"(b0), "r"(b1))

__device__ __forceinline__ uint32_t pbf2(float a, float b) {
    __nv_bfloat162 t = __floats2bfloat162_rn(a, b);
    return *reinterpret_cast<uint32_t*>(&t);
}

// =====================================================================
// Kernel 1: QKV projections. Q,K -> split bf16 [hi|lo]; V -> fp32
// =====================================================================
__global__ void proj_kernel(const float* __restrict__ Xq, const float* __restrict__ Xk,
                            const float* __restrict__ Xv,
                            const float* __restrict__ Wq, const float* __restrict__ Wk,
                            const float* __restrict__ Wv,
                            const float* __restrict__ bq, const float* __restrict__ bk,
                            const float* __restrict__ bv) {
    __shared__ float sW[DM*HID];
    __shared__ float sX[32*20];
    const int which = blockIdx.y;
    const float* X    = (which == 0) ? Xq : (which == 1) ? Xk : Xv;
    const float* W    = (which == 0) ? Wq : (which == 1) ? Wk : Wv;
    const float* bias = (which == 0) ? bq : (which == 1) ? bk : bv;

    const int t = threadIdx.x;
    for (int i = t; i < DM*HID; i += 256) sW[i] = W[i];
    const int base = blockIdx.x * 32;
    for (int i = t; i < 32*DM; i += 256) {
        int r = i / DM, m = i - r*DM;
        sX[r*20 + m] = X[(size_t)(base + r)*DM + m];
    }
    __syncthreads();

    const int bidx = base >> 10;
    const int lbase = base & 1023;
    #pragma unroll
    for (int cc = 0; cc < 2; cc++) {
        const int c = t + cc*256;
        const int h = c >> 6, d = c & 63;
        const float bval = bias[c];
        if (which < 2) {
            __nv_bfloat16* dp = (which == 0 ? g_qs : g_ks)
                + ((size_t)(bidx*NH + h)*LL + lbase)*128 + d;
            for (int r = 0; r < 32; r++) {
                float acc = bval;
                #pragma unroll
                for (int m = 0; m < DM; m++) acc += sX[r*20 + m] * sW[m*HID + c];
                __nv_bfloat16 hi = __float2bfloat16(acc);
                __nv_bfloat16 lo = __float2bfloat16(acc - __bfloat162float(hi));
                dp[(size_t)r*128]      = hi;
                dp[(size_t)r*128 + 64] = lo;
            }
        } else {
            float* dp = g_v + ((size_t)(bidx*NH + h)*LL + lbase)*DH + d;
            for (int r = 0; r < 32; r++) {
                float acc = bval;
                #pragma unroll
                for (int m = 0; m < DM; m++) acc += sX[r*20 + m] * sW[m*HID + c];
                dp[(size_t)r*DH] = acc;
            }
        }
    }
}

// =====================================================================
// Kernel 1b: V transpose  g_v[bh][l][d] fp32 -> g_vT[bh][d][l] bf16
// =====================================================================
__global__ void transpose_v_kernel() {
    __shared__ float ts[128*65];
    const int t = threadIdx.x;
    const int bh = blockIdx.y;
    const int lbase = blockIdx.x * 128;
    const float* src = g_v + ((size_t)bh*LL + lbase)*DH;
    #pragma unroll
    for (int j = 0; j < 8; j++) {
        int idx = t + j*256;
        int r = idx >> 4, d4 = (idx & 15)*4;
        float4 a = *(const float4*)(src + (size_t)r*DH + d4);
        ts[r*65 + d4 + 0] = a.x; ts[r*65 + d4 + 1] = a.y;
        ts[r*65 + d4 + 2] = a.z; ts[r*65 + d4 + 3] = a.w;
    }
    __syncthreads();
    #pragma unroll
    for (int j = 0; j < 4; j++) {
        int idx = t + j*256;
        int d = idx >> 4, c8 = (idx & 15)*8;
        uint4 o;
        o.x = pbf2(ts[(c8+0)*65 + d], ts[(c8+1)*65 + d]);
        o.y = pbf2(ts[(c8+2)*65 + d], ts[(c8+3)*65 + d]);
        o.z = pbf2(ts[(c8+4)*65 + d], ts[(c8+5)*65 + d]);
        o.w = pbf2(ts[(c8+6)*65 + d], ts[(c8+7)*65 + d]);
        *(uint4*)(g_vT + ((size_t)bh*DH + d)*LL + lbase + c8) = o;
    }
}

// =====================================================================
// Kernel 2: mma.sync attention, 32-q strips, full score row in smem.
// grid (32, 128), 256 threads, smem 214016.
// Single normalized attn write; no scale kernel.
// =====================================================================
#define SQ_  0u
#define SK0_ 12800u
#define SK1_ 38400u
#define SV0_ 64000u
#define SV1_ 73216u
#define SS_  82432u
#define SPITCH 1028
#define ATT_SMEM 214016

__device__ __forceinline__ void load_k(uint32_t sb, int buf, int cb, int bh, int t) {
    const uint32_t sk = sb + (buf ? SK1_ : SK0_);
    const __nv_bfloat16* ks = g_ks + ((size_t)bh*LL + cb)*128;
    #pragma unroll
    for (int j = 0; j < 6; j++) {                 // 64 keys x [hi|hi|lo] = 24 f4
        int idx = t + j*256; int key = idx/24, p = idx%24; int sf = (p < 8) ? p : p - 8;
        cp16(sk + key*400 + p*16, ks + (size_t)key*128 + sf*8);
    }
}
__device__ __forceinline__ void load_v(uint32_t sb, int buf, int cb, int bh, int t) {
    const uint32_t sv = sb + (buf ? SV1_ : SV0_);
    const __nv_bfloat16* vt = g_vT + (size_t)bh*DH*LL + cb;
    #pragma unroll
    for (int j = 0; j < 2; j++) {                 // 64 d x 64 keys = 8 f4
        int idx = t + j*256; int d = idx >> 3, p = idx & 7;
        cp16(sv + d*144 + p*16, vt + (size_t)d*LL + p*8);
    }
}

__global__ __launch_bounds__(256, 1)
void attn_kernel(const int* __restrict__ mask, float* __restrict__ attn_out) {
    extern __shared__ char smem[];
    __shared__ float sinv[MQ];
    const uint32_t sb = s2u(smem);
    const int t = threadIdx.x;
    const int wid = t >> 5, lane = t & 31;
    const int g = lane >> 2, m = lane & 3;
    const int mt = wid & 1, nq = wid >> 1;
    const int r1 = mt*16 + g, r2 = r1 + 8;
    const int bh = blockIdx.y, b = bh >> 3, h = bh & 7;
    const int qbase = blockIdx.x * MQ;
    const float INVSCALE = 0.13258252147247766f;   // sqrt(9/512)

    // ---- prologue: Q frags + K chunks 0,1 ----
    {
        const __nv_bfloat16* qs = g_qs + ((size_t)bh*LL + qbase)*128;
        #pragma unroll
        for (int j = 0; j < 3; j++) {             // 32 q x [hi|lo|hi] = 24 f4
            int idx = t + j*256; int row = idx/24, p = idx%24; int sf = (p < 16) ? p : p - 16;
            cp16(sb + SQ_ + row*400 + p*16, qs + (size_t)row*128 + sf*8);
        }
        load_k(sb, 0, 0, bh, t);
        CP_COMMIT();
        load_k(sb, 1, 64, bh, t);
        CP_COMMIT();
    }

    const uint32_t* Qp = (const uint32_t*)(smem + SQ_);
    float* S = (float*)(smem + SS_);

    // ================= scores: 16 chunks of 64 keys =================
    for (int tt = 0; tt < 16; tt++) {
        if (tt == 15) { CP_WAIT(0); } else { CP_WAIT(1); }
        __syncthreads();
        const uint32_t* Kp = (const uint32_t*)(smem + ((tt & 1) ? SK1_ : SK0_));
        float acc[2][4] = {};
        #pragma unroll
        for (int ks = 0; ks < 12; ks++) {
            uint32_t a0 = Qp[r1*100 + ks*8 + m];
            uint32_t a1 = Qp[r2*100 + ks*8 + m];
            uint32_t a2 = Qp[r1*100 + ks*8 + m + 4];
            uint32_t a3 = Qp[r2*100 + ks*8 + m + 4];
            #pragma unroll
            for (int ntl = 0; ntl < 2; ntl++) {
                const int key = (nq*2 + ntl)*8 + g;
                uint32_t b0 = Kp[key*100 + ks*8 + m];
                uint32_t b1 = Kp[key*100 + ks*8 + m + 4];
                MMA16816(acc[ntl], a0, a1, a2, a3, b0, b1);
            }
        }
        #pragma unroll
        for (int ntl = 0; ntl < 2; ntl++) {
            const int col = tt*64 + (nq*2 + ntl)*8 + 2*m;
            *(float2*)(S + r1*SPITCH + col) = make_float2(acc[ntl][0]*INVSCALE, acc[ntl][1]*INVSCALE);
            *(float2*)(S + r2*SPITCH + col) = make_float2(acc[ntl][2]*INVSCALE, acc[ntl][3]*INVSCALE);
        }
        __syncthreads();
        if (tt + 2 < 16) { load_k(sb, tt & 1, (tt+2)*64, bh, t); CP_COMMIT(); }
    }

    // ---- start streaming V during softmax ----
    load_v(sb, 0, 0, bh, t);  CP_COMMIT();
    load_v(sb, 1, 64, bh, t); CP_COMMIT();

    // ================= softmax: warp per 4 rows; single attn write =================
    for (int rr = 0; rr < 4; rr++) {
        const int row = wid*4 + rr;
        float* Sr = S + row*SPITCH;
        const int* mrow = mask + ((size_t)b*LL + qbase + row)*LL;
        float4 ev[8];
        float sum = 0.f;
        #pragma unroll
        for (int i = 0; i < 8; i++) {
            const int col = lane*4 + i*128;
            float4 s4 = *(float4*)(Sr + col);
            int4 mm = *(const int4*)(mrow + col);
            float4 e;
            e.x = mm.x ? 0.f : __expf(s4.x);
            e.y = mm.y ? 0.f : __expf(s4.y);
            e.z = mm.z ? 0.f : __expf(s4.z);
            e.w = mm.w ? 0.f : __expf(s4.w);
            ev[i] = e;
            sum += (e.x + e.y) + (e.z + e.w);
            *(float4*)(Sr + col) = e;              // unnormalized e kept for PV
        }
        #pragma unroll
        for (int o = 16; o; o >>= 1) sum += __shfl_xor_sync(~0u, sum, o);
        const float inv = 1.0f / sum;
        if (lane == 0) sinv[row] = inv;
        float* arow = attn_out + ((size_t)bh*LL + qbase + row)*LL;
        #pragma unroll
        for (int i = 0; i < 8; i++) {
            float4 p;
            p.x = ev[i].x*inv; p.y = ev[i].y*inv; p.z = ev[i].z*inv; p.w = ev[i].w*inv;
            *(float4*)(arow + lane*4 + i*128) = p;
        }
    }
    __syncthreads();

    // ================= PV: ctx = e @ V, scale by 1/sum =================
    float cacc[2][4] = {};
    for (int tt = 0; tt < 16; tt++) {
        if (tt == 15) { CP_WAIT(0); } else { CP_WAIT(1); }
        __syncthreads();
        const uint32_t* Vp = (const uint32_t*)(smem + ((tt & 1) ? SV1_ : SV0_));
        const int cb = tt*64;
        #pragma unroll
        for (int ks = 0; ks < 4; ks++) {
            const int kb = cb + ks*16 + 2*m;
            float2 sA0 = *(float2*)(S + r1*SPITCH + kb);
            float2 sA1 = *(float2*)(S + r2*SPITCH + kb);
            float2 sA2 = *(float2*)(S + r1*SPITCH + kb + 8);
            float2 sA3 = *(float2*)(S + r2*SPITCH + kb + 8);
            uint32_t a0 = pbf2(sA0.x, sA0.y);
            uint32_t a1 = pbf2(sA1.x, sA1.y);
            uint32_t a2 = pbf2(sA2.x, sA2.y);
            uint32_t a3 = pbf2(sA3.x, sA3.y);
            #pragma unroll
            for (int ntl = 0; ntl < 2; ntl++) {
                const int dd = (nq*2 + ntl)*8 + g;
                uint32_t b0 = Vp[dd*36 + ks*8 + m];
                uint32_t b1 = Vp[dd*36 + ks*8 + m + 4];
                MMA16816(cacc[ntl], a0, a1, a2, a3, b0, b1);
            }
        }
        __syncthreads();
        if (tt + 2 < 16) { load_v(sb, tt & 1, (tt+2)*64, bh, t); CP_COMMIT(); }
    }
    const float invA = sinv[r1], invB = sinv[r2];
    float* c1p = g_ctx + ((size_t)b*LL + qbase + r1)*HID + h*DH;
    float* c2p = g_ctx + ((size_t)b*LL + qbase + r2)*HID + h*DH;
    #pragma unroll
    for (int ntl = 0; ntl < 2; ntl++) {
        const int dcol = (nq*2 + ntl)*8 + 2*m;
        *(float2*)(c1p + dcol) = make_float2(cacc[ntl][0]*invA, cacc[ntl][1]*invA);
        *(float2*)(c2p + dcol) = make_float2(cacc[ntl][2]*invB, cacc[ntl][3]*invB);
    }
}

// =====================================================================
// Kernel 3: out = LN(ctx @ Wo + bo + residual). 256 thr, 8 tokens/block
// =====================================================================
__global__ void outproj_kernel(const float* __restrict__ Qin, const float* __restrict__ Wo,
                               const float* __restrict__ bo, const float* __restrict__ lng,
                               const float* __restrict__ lnb, float* __restrict__ out) {
    extern __shared__ float osm[];
    float* sWo = osm;
    float* scx = sWo + HID*DM;
    float* sx  = scx + 8*HID;
    const int t = threadIdx.x, warp = t >> 5, lane = t & 31;
    for (int i = t; i < HID*DM; i += 256) sWo[i] = Wo[i];
    const int n = blockIdx.x*8 + warp;
    #pragma unroll
    for (int k = 0; k < 4; k++)
        *(float4*)(scx + warp*HID + lane*4 + 128*k) =
            *(const float4*)(g_ctx + (size_t)n*HID + lane*4 + 128*k);
    __syncthreads();

    float x = 0.f;
    if (lane < DM) {
        float a0 = 0.f, a1 = 0.f, a2 = 0.f, a3 = 0.f;
        const float* cs = scx + warp*HID;
        for (int i = 0; i < HID; i += 4) {
            a0 += cs[i+0]*sWo[(i+0)*DM + lane];
            a1 += cs[i+1]*sWo[(i+1)*DM + lane];
            a2 += cs[i+2]*sWo[(i+2)*DM + lane];
            a3 += cs[i+3]*sWo[(i+3)*DM + lane];
        }
        x = (a0+a1) + (a2+a3) + bo[lane] + Qin[(size_t)n*DM + lane];
        sx[warp*20 + lane] = x;
    }
    __syncwarp();
    if (lane < DM) {
        float mu = 0.f;
        #pragma unroll
        for (int j = 0; j < DM; j++) mu += sx[warp*20 + j];
        mu *= (1.0f/19.0f);
        float var = 0.f;
        #pragma unroll
        for (int j = 0; j < DM; j++) { float d = sx[warp*20 + j] - mu; var += d*d; }
        var *= (1.0f/19.0f);
        out[(size_t)n*DM + lane] = (x - mu)*rsqrtf(var + 1e-5f)*lng[lane] + lnb[lane];
    }
}

// =====================================================================
// Kernel 4: residual = Q
// =====================================================================
__global__ void copy_res_kernel(const float* __restrict__ Qin, float* __restrict__ dst) {
    const size_t i = ((size_t)blockIdx.x*256 + threadIdx.x)*4;
    *(float4*)(dst + i) = *(const float4*)(Qin + i);
}

// =====================================================================
extern "C" void kernel_launch(void* const* d_in, const int* in_sizes, int n_in,
                              void* d_out, int out_size) {
    const float* Q   = (const float*)d_in[0];
    const float* K   = (const float*)d_in[1];
    const float* V   = (const float*)d_in[2];
    const int*  mask = (const int*)d_in[3];
    const float* Wq  = (const float*)d_in[4];
    const float* bq  = (const float*)d_in[5];
    const float* Wk  = (const float*)d_in[6];
    const float* bk  = (const float*)d_in[7];
    const float* Wv  = (const float*)d_in[8];
    const float* bv  = (const float*)d_in[9];
    const float* Wo  = (const float*)d_in[10];
    const float* bo  = (const float*)d_in[11];
    const float* lng = (const float*)d_in[12];
    const float* lnb = (const float*)d_in[13];

    float* out  = (float*)d_out;
    float* attn = out + OUT_ELEMS;
    float* res  = attn + ATTN_ELEMS;

    cudaFuncSetAttribute(attn_kernel, cudaFuncAttributeMaxDynamicSharedMemorySize, ATT_SMEM);
    const int OUT_SMEM = (HID*DM + 8*HID + 8*20) * (int)sizeof(float);
    cudaFuncSetAttribute(outproj_kernel, cudaFuncAttributeMaxDynamicSharedMemorySize, OUT_SMEM);

    proj_kernel<<<dim3(NTOK/32, 3), 256>>>(Q, K, V, Wq, Wk, Wv, bq, bk, bv);
    transpose_v_kernel<<<dim3(LL/128, BB*NH), 256>>>();
    attn_kernel<<<dim3(LL/MQ, BB*NH), 256, ATT_SMEM>>>(mask, attn);
    outproj_kernel<<<NTOK/8, 256, OUT_SMEM>>>(Q, Wo, bo, lng, lnb, out);
    copy_res_kernel<<<OUT_ELEMS/4/256, 256>>>(Q, res);
}

// round 14
// speedup vs baseline: 1.0073x; 1.0073x over previous
#include <cuda_runtime.h>
#include <cuda_bf16.h>
#include <cstdint>
#include <cstddef>

#define DM 19
#define HID 512
#define NH 8
#define DH 64
#define BB 16
#define LL 1024
#define NTOK (BB*LL)
#define MQ 32

#define OUT_ELEMS   (NTOK*DM)
#define ATTN_ELEMS  ((size_t)BB*NH*LL*LL)

// ---- scratch ----
__device__ __align__(256) __nv_bfloat16 g_qs[(size_t)BB*NH*LL*128];  // [bh][l][hi64|lo64]
__device__ __align__(256) __nv_bfloat16 g_ks[(size_t)BB*NH*LL*128];
__device__ __align__(256) float         g_v [(size_t)BB*NH*LL*DH];
__device__ __align__(256) __nv_bfloat16 g_vT[(size_t)BB*NH*DH*LL];   // [bh][d][l]
__device__ __align__(256) float         g_ctx[(size_t)NTOK*HID];

// ---- helpers ----
__device__ __forceinline__ uint32_t s2u(const void* p) {
    uint32_t a;
    asm("{ .reg .u64 t; cvta.to.shared.u64 t, %1; cvt.u32.u64 %0, t; }" : "=r"(a) : "l"(p));
    return a;
}
__device__ __forceinline__ void cp16(uint32_t dst, const void* src) {
    asm volatile("cp.async.cg.shared.global [%0], [%1], 16;"
                 :: "r"(dst), "l"(__cvta_generic_to_global(src)));
}
#define CP_COMMIT() asm volatile("cp.async.commit_group;" ::: "memory")
#define CP_WAIT(n)  asm volatile("cp.async.wait_group %0;" :: "n"(n) : "memory")

#define MMA16816(c, a0, a1, a2, a3, b0, b1)                                   \
    asm volatile("mma.sync.aligned.m16n8k16.row.col.f32.bf16.bf16.f32 "       \
        "{%0,%1,%2,%3}, {%4,%5,%6,%7}, {%8,%9}, {%0,%1,%2,%3};"               \
        : "+f"((c)[0]), "+f"((c)[1]), "+f"((c)[2]), "+f"((c)[3])              \
        : "r"(a0), "r"(a1), "r"(a2), "r"(a3), "r"(b0), "r"(b1))

__device__ __forceinline__ uint32_t pbf2(float a, float b) {
    __nv_bfloat162 t = __floats2bfloat162_rn(a, b);
    return *reinterpret_cast<uint32_t*>(&t);
}

// =====================================================================
// Kernel 1: QKV projections. Q,K -> split bf16 [hi|lo]; V -> fp32
// =====================================================================
__global__ void proj_kernel(const float* __restrict__ Xq, const float* __restrict__ Xk,
                            const float* __restrict__ Xv,
                            const float* __restrict__ Wq, const float* __restrict__ Wk,
                            const float* __restrict__ Wv,
                            const float* __restrict__ bq, const float* __restrict__ bk,
                            const float* __restrict__ bv) {
    __shared__ float sW[DM*HID];
    __shared__ float sX[32*20];
    const int which = blockIdx.y;
    const float* X    = (which == 0) ? Xq : (which == 1) ? Xk : Xv;
    const float* W    = (which == 0) ? Wq : (which == 1) ? Wk : Wv;
    const float* bias = (which == 0) ? bq : (which == 1) ? bk : bv;

    const int t = threadIdx.x;
    for (int i = t; i < DM*HID; i += 256) sW[i] = W[i];
    const int base = blockIdx.x * 32;
    for (int i = t; i < 32*DM; i += 256) {
        int r = i / DM, m = i - r*DM;
        sX[r*20 + m] = X[(size_t)(base + r)*DM + m];
    }
    __syncthreads();

    const int bidx = base >> 10;
    const int lbase = base & 1023;
    #pragma unroll
    for (int cc = 0; cc < 2; cc++) {
        const int c = t + cc*256;
        const int h = c >> 6, d = c & 63;
        const float bval = bias[c];
        if (which < 2) {
            __nv_bfloat16* dp = (which == 0 ? g_qs : g_ks)
                + ((size_t)(bidx*NH + h)*LL + lbase)*128 + d;
            for (int r = 0; r < 32; r++) {
                float acc = bval;
                #pragma unroll
                for (int m = 0; m < DM; m++) acc += sX[r*20 + m] * sW[m*HID + c];
                __nv_bfloat16 hi = __float2bfloat16(acc);
                __nv_bfloat16 lo = __float2bfloat16(acc - __bfloat162float(hi));
                dp[(size_t)r*128]      = hi;
                dp[(size_t)r*128 + 64] = lo;
            }
        } else {
            float* dp = g_v + ((size_t)(bidx*NH + h)*LL + lbase)*DH + d;
            for (int r = 0; r < 32; r++) {
                float acc = bval;
                #pragma unroll
                for (int m = 0; m < DM; m++) acc += sX[r*20 + m] * sW[m*HID + c];
                dp[(size_t)r*DH] = acc;
            }
        }
    }
}

// =====================================================================
// Kernel 1b: V transpose  g_v[bh][l][d] fp32 -> g_vT[bh][d][l] bf16
// =====================================================================
__global__ void transpose_v_kernel() {
    __shared__ float ts[128*65];
    const int t = threadIdx.x;
    const int bh = blockIdx.y;
    const int lbase = blockIdx.x * 128;
    const float* src = g_v + ((size_t)bh*LL + lbase)*DH;
    #pragma unroll
    for (int j = 0; j < 8; j++) {
        int idx = t + j*256;
        int r = idx >> 4, d4 = (idx & 15)*4;
        float4 a = *(const float4*)(src + (size_t)r*DH + d4);
        ts[r*65 + d4 + 0] = a.x; ts[r*65 + d4 + 1] = a.y;
        ts[r*65 + d4 + 2] = a.z; ts[r*65 + d4 + 3] = a.w;
    }
    __syncthreads();
    #pragma unroll
    for (int j = 0; j < 4; j++) {
        int idx = t + j*256;
        int d = idx >> 4, c8 = (idx & 15)*8;
        uint4 o;
        o.x = pbf2(ts[(c8+0)*65 + d], ts[(c8+1)*65 + d]);
        o.y = pbf2(ts[(c8+2)*65 + d], ts[(c8+3)*65 + d]);
        o.z = pbf2(ts[(c8+4)*65 + d], ts[(c8+5)*65 + d]);
        o.w = pbf2(ts[(c8+6)*65 + d], ts[(c8+7)*65 + d]);
        *(uint4*)(g_vT + ((size_t)bh*DH + d)*LL + lbase + c8) = o;
    }
}

// =====================================================================
// Kernel 2: mma.sync attention, 32-q strips, full score row in smem.
// grid (32, 128), 256 threads, smem 214016.
// Single normalized attn write; no scale kernel.
// =====================================================================
#define SQ_  0u
#define SK0_ 12800u
#define SK1_ 38400u
#define SV0_ 64000u
#define SV1_ 73216u
#define SS_  82432u
#define SPITCH 1028
#define ATT_SMEM 214016

__device__ __forceinline__ void load_k(uint32_t sb, int buf, int cb, int bh, int t) {
    const uint32_t sk = sb + (buf ? SK1_ : SK0_);
    const __nv_bfloat16* ks = g_ks + ((size_t)bh*LL + cb)*128;
    #pragma unroll
    for (int j = 0; j < 6; j++) {                 // 64 keys x [hi|hi|lo] = 24 f4
        int idx = t + j*256; int key = idx/24, p = idx%24; int sf = (p < 8) ? p : p - 8;
        cp16(sk + key*400 + p*16, ks + (size_t)key*128 + sf*8);
    }
}
__device__ __forceinline__ void load_v(uint32_t sb, int buf, int cb, int bh, int t) {
    const uint32_t sv = sb + (buf ? SV1_ : SV0_);
    const __nv_bfloat16* vt = g_vT + (size_t)bh*DH*LL + cb;
    #pragma unroll
    for (int j = 0; j < 2; j++) {                 // 64 d x 64 keys = 8 f4
        int idx = t + j*256; int d = idx >> 3, p = idx & 7;
        cp16(sv + d*144 + p*16, vt + (size_t)d*LL + p*8);
    }
}

__global__ __launch_bounds__(256, 1)
void attn_kernel(const int* __restrict__ mask, float* __restrict__ attn_out) {
    extern __shared__ char smem[];
    __shared__ float sinv[MQ];
    const uint32_t sb = s2u(smem);
    const int t = threadIdx.x;
    const int wid = t >> 5, lane = t & 31;
    const int g = lane >> 2, m = lane & 3;
    const int mt = wid & 1, nq = wid >> 1;
    const int r1 = mt*16 + g, r2 = r1 + 8;
    const int bh = blockIdx.y, b = bh >> 3, h = bh & 7;
    const int qbase = blockIdx.x * MQ;
    const float INVSCALE = 0.13258252147247766f;   // sqrt(9/512)

    // ---- prologue: Q frags + K chunks 0,1 ----
    {
        const __nv_bfloat16* qs = g_qs + ((size_t)bh*LL + qbase)*128;
        #pragma unroll
        for (int j = 0; j < 3; j++) {             // 32 q x [hi|lo|hi] = 24 f4
            int idx = t + j*256; int row = idx/24, p = idx%24; int sf = (p < 16) ? p : p - 16;
            cp16(sb + SQ_ + row*400 + p*16, qs + (size_t)row*128 + sf*8);
        }
        load_k(sb, 0, 0, bh, t);
        CP_COMMIT();
        load_k(sb, 1, 64, bh, t);
        CP_COMMIT();
    }

    const uint32_t* Qp = (const uint32_t*)(smem + SQ_);
    float* S = (float*)(smem + SS_);

    // ================= scores: 16 chunks of 64 keys =================
    for (int tt = 0; tt < 16; tt++) {
        if (tt == 15) { CP_WAIT(0); } else { CP_WAIT(1); }
        __syncthreads();
        const uint32_t* Kp = (const uint32_t*)(smem + ((tt & 1) ? SK1_ : SK0_));
        float acc[2][4] = {};
        #pragma unroll
        for (int ks = 0; ks < 12; ks++) {
            uint32_t a0 = Qp[r1*100 + ks*8 + m];
            uint32_t a1 = Qp[r2*100 + ks*8 + m];
            uint32_t a2 = Qp[r1*100 + ks*8 + m + 4];
            uint32_t a3 = Qp[r2*100 + ks*8 + m + 4];
            #pragma unroll
            for (int ntl = 0; ntl < 2; ntl++) {
                const int key = (nq*2 + ntl)*8 + g;
                uint32_t b0 = Kp[key*100 + ks*8 + m];
                uint32_t b1 = Kp[key*100 + ks*8 + m + 4];
                MMA16816(acc[ntl], a0, a1, a2, a3, b0, b1);
            }
        }
        #pragma unroll
        for (int ntl = 0; ntl < 2; ntl++) {
            const int col = tt*64 + (nq*2 + ntl)*8 + 2*m;
            *(float2*)(S + r1*SPITCH + col) = make_float2(acc[ntl][0]*INVSCALE, acc[ntl][1]*INVSCALE);
            *(float2*)(S + r2*SPITCH + col) = make_float2(acc[ntl][2]*INVSCALE, acc[ntl][3]*INVSCALE);
        }
        __syncthreads();
        if (tt + 2 < 16) { load_k(sb, tt & 1, (tt+2)*64, bh, t); CP_COMMIT(); }
    }

    // ---- start streaming V during softmax ----
    load_v(sb, 0, 0, bh, t);  CP_COMMIT();
    load_v(sb, 1, 64, bh, t); CP_COMMIT();

    // ================= softmax: warp per 4 rows; single attn write =================
    for (int rr = 0; rr < 4; rr++) {
        const int row = wid*4 + rr;
        float* Sr = S + row*SPITCH;
        const int* mrow = mask + ((size_t)b*LL + qbase + row)*LL;
        float4 ev[8];
        float sum = 0.f;
        #pragma unroll
        for (int i = 0; i < 8; i++) {
            const int col = lane*4 + i*128;
            float4 s4 = *(float4*)(Sr + col);
            int4 mm = *(const int4*)(mrow + col);
            float4 e;
            e.x = mm.x ? 0.f : __expf(s4.x);
            e.y = mm.y ? 0.f : __expf(s4.y);
            e.z = mm.z ? 0.f : __expf(s4.z);
            e.w = mm.w ? 0.f : __expf(s4.w);
            ev[i] = e;
            sum += (e.x + e.y) + (e.z + e.w);
            *(float4*)(Sr + col) = e;              // unnormalized e kept for PV
        }
        #pragma unroll
        for (int o = 16; o; o >>= 1) sum += __shfl_xor_sync(~0u, sum, o);
        const float inv = 1.0f / sum;
        if (lane == 0) sinv[row] = inv;
        float* arow = attn_out + ((size_t)bh*LL + qbase + row)*LL;
        #pragma unroll
        for (int i = 0; i < 8; i++) {
            float4 p;
            p.x = ev[i].x*inv; p.y = ev[i].y*inv; p.z = ev[i].z*inv; p.w = ev[i].w*inv;
            *(float4*)(arow + lane*4 + i*128) = p;
        }
    }
    __syncthreads();

    // ================= PV: ctx = e @ V, scale by 1/sum =================
    float cacc[2][4] = {};
    for (int tt = 0; tt < 16; tt++) {
        if (tt == 15) { CP_WAIT(0); } else { CP_WAIT(1); }
        __syncthreads();
        const uint32_t* Vp = (const uint32_t*)(smem + ((tt & 1) ? SV1_ : SV0_));
        const int cb = tt*64;
        #pragma unroll
        for (int ks = 0; ks < 4; ks++) {
            const int kb = cb + ks*16 + 2*m;
            float2 sA0 = *(float2*)(S + r1*SPITCH + kb);
            float2 sA1 = *(float2*)(S + r2*SPITCH + kb);
            float2 sA2 = *(float2*)(S + r1*SPITCH + kb + 8);
            float2 sA3 = *(float2*)(S + r2*SPITCH + kb + 8);
            uint32_t a0 = pbf2(sA0.x, sA0.y);
            uint32_t a1 = pbf2(sA1.x, sA1.y);
            uint32_t a2 = pbf2(sA2.x, sA2.y);
            uint32_t a3 = pbf2(sA3.x, sA3.y);
            #pragma unroll
            for (int ntl = 0; ntl < 2; ntl++) {
                const int dd = (nq*2 + ntl)*8 + g;
                uint32_t b0 = Vp[dd*36 + ks*8 + m];
                uint32_t b1 = Vp[dd*36 + ks*8 + m + 4];
                MMA16816(cacc[ntl], a0, a1, a2, a3, b0, b1);
            }
        }
        __syncthreads();
        if (tt + 2 < 16) { load_v(sb, tt & 1, (tt+2)*64, bh, t); CP_COMMIT(); }
    }
    const float invA = sinv[r1], invB = sinv[r2];
    float* c1p = g_ctx + ((size_t)b*LL + qbase + r1)*HID + h*DH;
    float* c2p = g_ctx + ((size_t)b*LL + qbase + r2)*HID + h*DH;
    #pragma unroll
    for (int ntl = 0; ntl < 2; ntl++) {
        const int dcol = (nq*2 + ntl)*8 + 2*m;
        *(float2*)(c1p + dcol) = make_float2(cacc[ntl][0]*invA, cacc[ntl][1]*invA);
        *(float2*)(c2p + dcol) = make_float2(cacc[ntl][2]*invB, cacc[ntl][3]*invB);
    }
}

// =====================================================================
// Kernel 3: out = LN(ctx @ Wo + bo + residual). 256 thr, 8 tokens/block
// =====================================================================
__global__ void outproj_kernel(const float* __restrict__ Qin, const float* __restrict__ Wo,
                               const float* __restrict__ bo, const float* __restrict__ lng,
                               const float* __restrict__ lnb, float* __restrict__ out) {
    extern __shared__ float osm[];
    float* sWo = osm;
    float* scx = sWo + HID*DM;
    float* sx  = scx + 8*HID;
    const int t = threadIdx.x, warp = t >> 5, lane = t & 31;
    for (int i = t; i < HID*DM; i += 256) sWo[i] = Wo[i];
    const int n = blockIdx.x*8 + warp;
    #pragma unroll
    for (int k = 0; k < 4; k++)
        *(float4*)(scx + warp*HID + lane*4 + 128*k) =
            *(const float4*)(g_ctx + (size_t)n*HID + lane*4 + 128*k);
    __syncthreads();

    float x = 0.f;
    if (lane < DM) {
        float a0 = 0.f, a1 = 0.f, a2 = 0.f, a3 = 0.f;
        const float* cs = scx + warp*HID;
        for (int i = 0; i < HID; i += 4) {
            a0 += cs[i+0]*sWo[(i+0)*DM + lane];
            a1 += cs[i+1]*sWo[(i+1)*DM + lane];
            a2 += cs[i+2]*sWo[(i+2)*DM + lane];
            a3 += cs[i+3]*sWo[(i+3)*DM + lane];
        }
        x = (a0+a1) + (a2+a3) + bo[lane] + Qin[(size_t)n*DM + lane];
        sx[warp*20 + lane] = x;
    }
    __syncwarp();
    if (lane < DM) {
        float mu = 0.f;
        #pragma unroll
        for (int j = 0; j < DM; j++) mu += sx[warp*20 + j];
        mu *= (1.0f/19.0f);
        float var = 0.f;
        #pragma unroll
        for (int j = 0; j < DM; j++) { float d = sx[warp*20 + j] - mu; var += d*d; }
        var *= (1.0f/19.0f);
        out[(size_t)n*DM + lane] = (x - mu)*rsqrtf(var + 1e-5f)*lng[lane] + lnb[lane];
    }
}

// =====================================================================
// Kernel 4: residual = Q
// =====================================================================
__global__ void copy_res_kernel(const float* __restrict__ Qin, float* __restrict__ dst) {
    const size_t i = ((size_t)blockIdx.x*256 + threadIdx.x)*4;
    *(float4*)(dst + i) = *(const float4*)(Qin + i);
}

// =====================================================================
extern "C" void kernel_launch(void* const* d_in, const int* in_sizes, int n_in,
                              void* d_out, int out_size) {
    const float* Q   = (const float*)d_in[0];
    const float* K   = (const float*)d_in[1];
    const float* V   = (const float*)d_in[2];
    const int*  mask = (const int*)d_in[3];
    const float* Wq  = (const float*)d_in[4];
    const float* bq  = (const float*)d_in[5];
    const float* Wk  = (const float*)d_in[6];
    const float* bk  = (const float*)d_in[7];
    const float* Wv  = (const float*)d_in[8];
    const float* bv  = (const float*)d_in[9];
    const float* Wo  = (const float*)d_in[10];
    const float* bo  = (const float*)d_in[11];
    const float* lng = (const float*)d_in[12];
    const float* lnb = (const float*)d_in[13];

    float* out  = (float*)d_out;
    float* attn = out + OUT_ELEMS;
    float* res  = attn + ATTN_ELEMS;

    cudaFuncSetAttribute(attn_kernel, cudaFuncAttributeMaxDynamicSharedMemorySize, ATT_SMEM);
    const int OUT_SMEM = (HID*DM + 8*HID + 8*20) * (int)sizeof(float);
    cudaFuncSetAttribute(outproj_kernel, cudaFuncAttributeMaxDynamicSharedMemorySize, OUT_SMEM);

    proj_kernel<<<dim3(NTOK/32, 3), 256>>>(Q, K, V, Wq, Wk, Wv, bq, bk, bv);
    transpose_v_kernel<<<dim3(LL/128, BB*NH), 256>>>();
    attn_kernel<<<dim3(LL/MQ, BB*NH), 256, ATT_SMEM>>>(mask, attn);
    outproj_kernel<<<NTOK/8, 256, OUT_SMEM>>>(Q, Wo, bo, lng, lnb, out);
    copy_res_kernel<<<OUT_ELEMS/4/256, 256>>>(Q, res);
}

// round 15
// speedup vs baseline: 1.2286x; 1.2196x over previous
#include <cuda_runtime.h>
#include <cuda_bf16.h>
#include <cstdint>
#include <cstddef>

#define DM 19
#define HID 512
#define NH 8
#define DH 64
#define BB 16
#define LL 1024
#define NTOK (BB*LL)
#define QT 128

#define OUT_ELEMS   (NTOK*DM)
#define ATTN_ELEMS  ((size_t)BB*NH*LL*LL)

// ---- scratch ----
__device__ __align__(256) __nv_bfloat16 g_qs[(size_t)BB*NH*LL*128];  // [bh][l][hi64|lo64]
__device__ __align__(256) __nv_bfloat16 g_ks[(size_t)BB*NH*LL*128];
__device__ __align__(256) float         g_v [(size_t)BB*NH*LL*DH];
__device__ __align__(256) __nv_bfloat16 g_vT[(size_t)BB*NH*DH*LL];   // [bh][d][l]
__device__ __align__(256) float         g_ctx[(size_t)NTOK*HID];
__device__ __align__(256) float         g_inv[(size_t)BB*NH*LL];     // 1/rowsum

// ---- helpers ----
__device__ __forceinline__ uint32_t s2u(const void* p) {
    uint32_t a;
    asm("{ .reg .u64 t; cvta.to.shared.u64 t, %1; cvt.u32.u64 %0, t; }" : "=r"(a) : "l"(p));
    return a;
}
__device__ __forceinline__ void cp16(uint32_t dst, const void* src) {
    asm volatile("cp.async.cg.shared.global [%0], [%1], 16;"
                 :: "r"(dst), "l"(__cvta_generic_to_global(src)));
}
#define CP_COMMIT() asm volatile("cp.async.commit_group;" ::: "memory")
#define CP_WAIT(n)  asm volatile("cp.async.wait_group %0;" :: "n"(n) : "memory")

#define MMA16816(c, a0, a1, a2, a3, b0, b1)                                   \
    asm volatile("mma.sync.aligned.m16n8k16.row.col.f32.bf16.bf16.f32 "       \
        "{%0,%1,%2,%3}, {%4,%5,%6,%7}, {%8,%9}, {%0,%1,%2,%3};"               \
        : "+f"((c)[0]), "+f"((c)[1]), "+f"((c)[2]), "+f"((c)[3])              \
        : "r"(a0), "r"(a1), "r"(a2), "r"(a3), "r"(b0), "r"(b1))

__device__ __forceinline__ uint32_t pbf2(float a, float b) {
    __nv_bfloat162 t = __floats2bfloat162_rn(a, b);
    return *reinterpret_cast<uint32_t*>(&t);
}

// =====================================================================
// Kernel 1: QKV projections. Q,K -> split bf16 [hi|lo]; V -> fp32
// =====================================================================
__global__ void proj_kernel(const float* __restrict__ Xq, const float* __restrict__ Xk,
                            const float* __restrict__ Xv,
                            const float* __restrict__ Wq, const float* __restrict__ Wk,
                            const float* __restrict__ Wv,
                            const float* __restrict__ bq, const float* __restrict__ bk,
                            const float* __restrict__ bv) {
    __shared__ float sW[DM*HID];
    __shared__ float sX[32*20];
    const int which = blockIdx.y;
    const float* X    = (which == 0) ? Xq : (which == 1) ? Xk : Xv;
    const float* W    = (which == 0) ? Wq : (which == 1) ? Wk : Wv;
    const float* bias = (which == 0) ? bq : (which == 1) ? bk : bv;

    const int t = threadIdx.x;
    for (int i = t; i < DM*HID; i += 256) sW[i] = W[i];
    const int base = blockIdx.x * 32;
    for (int i = t; i < 32*DM; i += 256) {
        int r = i / DM, m = i - r*DM;
        sX[r*20 + m] = X[(size_t)(base + r)*DM + m];
    }
    __syncthreads();

    const int bidx = base >> 10;
    const int lbase = base & 1023;
    #pragma unroll
    for (int cc = 0; cc < 2; cc++) {
        const int c = t + cc*256;
        const int h = c >> 6, d = c & 63;
        const float bval = bias[c];
        if (which < 2) {
            __nv_bfloat16* dp = (which == 0 ? g_qs : g_ks)
                + ((size_t)(bidx*NH + h)*LL + lbase)*128 + d;
            for (int r = 0; r < 32; r++) {
                float acc = bval;
                #pragma unroll
                for (int m = 0; m < DM; m++) acc += sX[r*20 + m] * sW[m*HID + c];
                __nv_bfloat16 hi = __float2bfloat16(acc);
                __nv_bfloat16 lo = __float2bfloat16(acc - __bfloat162float(hi));
                dp[(size_t)r*128]      = hi;
                dp[(size_t)r*128 + 64] = lo;
            }
        } else {
            float* dp = g_v + ((size_t)(bidx*NH + h)*LL + lbase)*DH + d;
            for (int r = 0; r < 32; r++) {
                float acc = bval;
                #pragma unroll
                for (int m = 0; m < DM; m++) acc += sX[r*20 + m] * sW[m*HID + c];
                dp[(size_t)r*DH] = acc;
            }
        }
    }
}

// =====================================================================
// Kernel 1b: V transpose  g_v[bh][l][d] fp32 -> g_vT[bh][d][l] bf16
// =====================================================================
__global__ void transpose_v_kernel() {
    __shared__ float ts[128*65];
    const int t = threadIdx.x;
    const int bh = blockIdx.y;
    const int lbase = blockIdx.x * 128;
    const float* src = g_v + ((size_t)bh*LL + lbase)*DH;
    #pragma unroll
    for (int j = 0; j < 8; j++) {
        int idx = t + j*256;
        int r = idx >> 4, d4 = (idx & 15)*4;
        float4 a = *(const float4*)(src + (size_t)r*DH + d4);
        ts[r*65 + d4 + 0] = a.x; ts[r*65 + d4 + 1] = a.y;
        ts[r*65 + d4 + 2] = a.z; ts[r*65 + d4 + 3] = a.w;
    }
    __syncthreads();
    #pragma unroll
    for (int j = 0; j < 4; j++) {
        int idx = t + j*256;
        int d = idx >> 4, c8 = (idx & 15)*8;
        uint4 o;
        o.x = pbf2(ts[(c8+0)*65 + d], ts[(c8+1)*65 + d]);
        o.y = pbf2(ts[(c8+2)*65 + d], ts[(c8+3)*65 + d]);
        o.z = pbf2(ts[(c8+4)*65 + d], ts[(c8+5)*65 + d]);
        o.w = pbf2(ts[(c8+6)*65 + d], ts[(c8+7)*65 + d]);
        *(uint4*)(g_vT + ((size_t)bh*DH + d)*LL + lbase + c8) = o;
    }
}

// =====================================================================
// Kernel 2: mma.sync attention. grid (8, 128), 512 threads, smem 208896
// Warp pair per 16-q tile; each warp owns half the 64-key chunk.
// Writes UNNORMALIZED e to attn + 1/rowsum to g_inv; ctx to g_ctx.
// =====================================================================
#define SQ_  0u
#define SK0_ 51200u
#define SK1_ 76800u
#define SV0_ 102400u
#define SV1_ 111616u
#define SM0_ 120832u
#define SM1_ 155648u
#define SP_  190464u
#define ATT_SMEM 208896

__device__ __forceinline__ void load_kvm(uint32_t sb, int buf, int cb, int bh, int b,
                                         int qbase, const int* __restrict__ mask, int t) {
    const uint32_t sk = sb + (buf ? SK1_ : SK0_);
    const uint32_t sv = sb + (buf ? SV1_ : SV0_);
    const uint32_t sm = sb + (buf ? SM1_ : SM0_);
    const __nv_bfloat16* ks = g_ks + ((size_t)bh*LL + cb)*128;
    #pragma unroll
    for (int j = 0; j < 3; j++) {                        // K: 64 keys x 24 f4
        int idx = t + j*512; int key = idx/24, p = idx%24; int sf = (p < 8) ? p : p - 8;
        cp16(sk + key*400 + p*16, ks + (size_t)key*128 + sf*8);
    }
    const __nv_bfloat16* vt = g_vT + (size_t)bh*DH*LL + cb;
    {                                                    // V: 64 d x 8 f4
        int d = t >> 3, p = t & 7;
        cp16(sv + d*144 + p*16, vt + (size_t)d*LL + p*8);
    }
    const int* mp = mask + ((size_t)b*LL + qbase)*LL + cb;
    #pragma unroll
    for (int j = 0; j < 4; j++) {                        // mask: 128 q x 16 f4
        int idx = t + j*512; int row = idx >> 4, p = idx & 15;
        cp16(sm + row*272 + p*16, mp + (size_t)row*LL + p*4);
    }
}

__global__ __launch_bounds__(512, 1)
void attn_kernel(const int* __restrict__ mask, float* __restrict__ attn_out) {
    extern __shared__ char smem[];
    __shared__ float ssum[2][QT];
    const uint32_t sb = s2u(smem);
    const int t = threadIdx.x;
    const int wid = t >> 5, lane = t & 31;
    const int g = lane >> 2, m = lane & 3;
    const int qt = wid >> 1, half = wid & 1;
    const int bh = blockIdx.y, b = bh >> 3, h = bh & 7;
    const int qbase = blockIdx.x * QT;
    const int r1 = qt*16 + g, r2 = r1 + 8;
    const float INVSCALE = 0.13258252147247766f;   // sqrt(9/512)

    // prologue
    {
        const __nv_bfloat16* qs = g_qs + ((size_t)bh*LL + qbase)*128;
        #pragma unroll
        for (int j = 0; j < 6; j++) {                    // Q: [hi|lo|hi], 128 q x 24 f4
            int idx = t + j*512; int row = idx/24, p = idx%24; int sf = (p < 16) ? p : p - 16;
            cp16(sb + SQ_ + row*400 + p*16, qs + (size_t)row*128 + sf*8);
        }
        load_kvm(sb, 0, 0, bh, b, qbase, mask, t);
        CP_COMMIT();
        load_kvm(sb, 1, 64, bh, b, qbase, mask, t);
        CP_COMMIT();
    }

    const uint32_t* Qp = (const uint32_t*)(smem + SQ_);
    uint32_t* Pp = (uint32_t*)(smem + SP_);
    float cacc[8][4] = {};
    float sumA = 0.f, sumB = 0.f;
    const size_t bhrow = (size_t)bh*LL + qbase;

    for (int tt = 0; tt < 16; tt++) {
        if (tt == 15) { CP_WAIT(0); } else { CP_WAIT(1); }
        __syncthreads();
        const int buf = tt & 1;
        const uint32_t* Kp = (const uint32_t*)(smem + (buf ? SK1_ : SK0_));
        const uint32_t* Vp = (const uint32_t*)(smem + (buf ? SV1_ : SV0_));
        const int*      Mp = (const int*)     (smem + (buf ? SM1_ : SM0_));
        const int cb = tt*64;

        // ---- scores: own key half, 4 n-tiles x 12 k-steps ----
        float acc[4][4] = {};
        #pragma unroll
        for (int ks = 0; ks < 12; ks++) {
            uint32_t a0 = Qp[r1*100 + ks*8 + m];
            uint32_t a1 = Qp[r2*100 + ks*8 + m];
            uint32_t a2 = Qp[r1*100 + ks*8 + m + 4];
            uint32_t a3 = Qp[r2*100 + ks*8 + m + 4];
            #pragma unroll
            for (int nt = 0; nt < 4; nt++) {
                const int key = half*32 + nt*8 + g;
                uint32_t b0 = Kp[key*100 + ks*8 + m];
                uint32_t b1 = Kp[key*100 + ks*8 + m + 4];
                MMA16816(acc[nt], a0, a1, a2, a3, b0, b1);
            }
        }
        // ---- mask + exp + sums + attn(e) store + P(bf16) ----
        #pragma unroll
        for (int nt = 0; nt < 4; nt++) {
            const int keyc = half*32 + nt*8 + 2*m;
            int2 mA = *(const int2*)(Mp + r1*68 + keyc);
            int2 mB = *(const int2*)(Mp + r2*68 + keyc);
            float e00 = mA.x ? 0.f : __expf(acc[nt][0]*INVSCALE);
            float e01 = mA.y ? 0.f : __expf(acc[nt][1]*INVSCALE);
            float e10 = mB.x ? 0.f : __expf(acc[nt][2]*INVSCALE);
            float e11 = mB.y ? 0.f : __expf(acc[nt][3]*INVSCALE);
            sumA += e00 + e01; sumB += e10 + e11;
            *(float2*)(attn_out + (bhrow + r1)*LL + cb + keyc) = make_float2(e00, e01);
            *(float2*)(attn_out + (bhrow + r2)*LL + cb + keyc) = make_float2(e10, e11);
            Pp[r1*36 + (half*4 + nt)*4 + m] = pbf2(e00, e01);
            Pp[r2*36 + (half*4 + nt)*4 + m] = pbf2(e10, e11);
        }
        __syncwarp();
        // ---- PV: own 2 k-steps, all 8 d-tiles ----
        #pragma unroll
        for (int ksl = 0; ksl < 2; ksl++) {
            const int ks = half*2 + ksl;
            uint32_t a0 = Pp[r1*36 + ks*8 + m];
            uint32_t a1 = Pp[r2*36 + ks*8 + m];
            uint32_t a2 = Pp[r1*36 + ks*8 + m + 4];
            uint32_t a3 = Pp[r2*36 + ks*8 + m + 4];
            #pragma unroll
            for (int nt = 0; nt < 8; nt++) {
                const int dd = nt*8 + g;
                uint32_t b0 = Vp[dd*36 + ks*8 + m];
                uint32_t b1 = Vp[dd*36 + ks*8 + m + 4];
                MMA16816(cacc[nt], a0, a1, a2, a3, b0, b1);
            }
        }
        __syncthreads();
        if (tt + 2 < 16) { load_kvm(sb, buf, (tt+2)*64, bh, b, qbase, mask, t); CP_COMMIT(); }
    }

    // ---- row sums (quad covers own key half; combine halves via smem) ----
    sumA += __shfl_xor_sync(~0u, sumA, 1); sumA += __shfl_xor_sync(~0u, sumA, 2);
    sumB += __shfl_xor_sync(~0u, sumB, 1); sumB += __shfl_xor_sync(~0u, sumB, 2);
    if (m == 0) { ssum[half][r1] = sumA; ssum[half][r2] = sumB; }
    __syncthreads();

    // ---- combine ctx halves through smem (K buffers are free now) ----
    float* cbuf = (float*)(smem + SK0_);    // pitch 66 (conflict-free)
    if (half == 0) {
        #pragma unroll
        for (int nt = 0; nt < 8; nt++) {
            *(float2*)(cbuf + r1*66 + nt*8 + 2*m) = make_float2(cacc[nt][0], cacc[nt][1]);
            *(float2*)(cbuf + r2*66 + nt*8 + 2*m) = make_float2(cacc[nt][2], cacc[nt][3]);
        }
    }
    __syncthreads();
    if (half == 1) {
        const float invA = 1.0f / (ssum[0][r1] + ssum[1][r1]);
        const float invB = 1.0f / (ssum[0][r2] + ssum[1][r2]);
        if (m == 0) {
            g_inv[bhrow + r1] = invA;
            g_inv[bhrow + r2] = invB;
        }
        float* c1p = g_ctx + ((size_t)b*LL + qbase + r1)*HID + h*DH;
        float* c2p = g_ctx + ((size_t)b*LL + qbase + r2)*HID + h*DH;
        #pragma unroll
        for (int nt = 0; nt < 8; nt++) {
            float2 p1 = *(float2*)(cbuf + r1*66 + nt*8 + 2*m);
            float2 p2 = *(float2*)(cbuf + r2*66 + nt*8 + 2*m);
            *(float2*)(c1p + nt*8 + 2*m) = make_float2((p1.x + cacc[nt][0])*invA,
                                                       (p1.y + cacc[nt][1])*invA);
            *(float2*)(c2p + nt*8 + 2*m) = make_float2((p2.x + cacc[nt][2])*invB,
                                                       (p2.y + cacc[nt][3])*invB);
        }
    }
}

// =====================================================================
// Kernel 2b: attn *= 1/rowsum  (in-place stream, DRAM-roofline)
// =====================================================================
__global__ void attn_scale_kernel(float* __restrict__ attn) {
    const size_t i = ((size_t)blockIdx.x*256 + threadIdx.x);
    const size_t base = i*4;
    const float inv = g_inv[base >> 10];
    float4 v = *(float4*)(attn + base);
    v.x *= inv; v.y *= inv; v.z *= inv; v.w *= inv;
    *(float4*)(attn + base) = v;
}

// =====================================================================
// Kernel 3: out = LN(ctx @ Wo + bo + residual). 256 thr, 8 tokens/block
// =====================================================================
__global__ void outproj_kernel(const float* __restrict__ Qin, const float* __restrict__ Wo,
                               const float* __restrict__ bo, const float* __restrict__ lng,
                               const float* __restrict__ lnb, float* __restrict__ out) {
    extern __shared__ float osm[];
    float* sWo = osm;
    float* scx = sWo + HID*DM;
    float* sx  = scx + 8*HID;
    const int t = threadIdx.x, warp = t >> 5, lane = t & 31;
    for (int i = t; i < HID*DM; i += 256) sWo[i] = Wo[i];
    const int n = blockIdx.x*8 + warp;
    #pragma unroll
    for (int k = 0; k < 4; k++)
        *(float4*)(scx + warp*HID + lane*4 + 128*k) =
            *(const float4*)(g_ctx + (size_t)n*HID + lane*4 + 128*k);
    __syncthreads();

    float x = 0.f;
    if (lane < DM) {
        float a0 = 0.f, a1 = 0.f, a2 = 0.f, a3 = 0.f;
        const float* cs = scx + warp*HID;
        for (int i = 0; i < HID; i += 4) {
            a0 += cs[i+0]*sWo[(i+0)*DM + lane];
            a1 += cs[i+1]*sWo[(i+1)*DM + lane];
            a2 += cs[i+2]*sWo[(i+2)*DM + lane];
            a3 += cs[i+3]*sWo[(i+3)*DM + lane];
        }
        x = (a0+a1) + (a2+a3) + bo[lane] + Qin[(size_t)n*DM + lane];
        sx[warp*20 + lane] = x;
    }
    __syncwarp();
    if (lane < DM) {
        float mu = 0.f;
        #pragma unroll
        for (int j = 0; j < DM; j++) mu += sx[warp*20 + j];
        mu *= (1.0f/19.0f);
        float var = 0.f;
        #pragma unroll
        for (int j = 0; j < DM; j++) { float d = sx[warp*20 + j] - mu; var += d*d; }
        var *= (1.0f/19.0f);
        out[(size_t)n*DM + lane] = (x - mu)*rsqrtf(var + 1e-5f)*lng[lane] + lnb[lane];
    }
}

// =====================================================================
// Kernel 4: residual = Q
// =====================================================================
__global__ void copy_res_kernel(const float* __restrict__ Qin, float* __restrict__ dst) {
    const size_t i = ((size_t)blockIdx.x*256 + threadIdx.x)*4;
    *(float4*)(dst + i) = *(const float4*)(Qin + i);
}

// =====================================================================
extern "C" void kernel_launch(void* const* d_in, const int* in_sizes, int n_in,
                              void* d_out, int out_size) {
    const float* Q   = (const float*)d_in[0];
    const float* K   = (const float*)d_in[1];
    const float* V   = (const float*)d_in[2];
    const int*  mask = (const int*)d_in[3];
    const float* Wq  = (const float*)d_in[4];
    const float* bq  = (const float*)d_in[5];
    const float* Wk  = (const float*)d_in[6];
    const float* bk  = (const float*)d_in[7];
    const float* Wv  = (const float*)d_in[8];
    const float* bv  = (const float*)d_in[9];
    const float* Wo  = (const float*)d_in[10];
    const float* bo  = (const float*)d_in[11];
    const float* lng = (const float*)d_in[12];
    const float* lnb = (const float*)d_in[13];

    float* out  = (float*)d_out;
    float* attn = out + OUT_ELEMS;
    float* res  = attn + ATTN_ELEMS;

    cudaFuncSetAttribute(attn_kernel, cudaFuncAttributeMaxDynamicSharedMemorySize, ATT_SMEM);
    const int OUT_SMEM = (HID*DM + 8*HID + 8*20) * (int)sizeof(float);
    cudaFuncSetAttribute(outproj_kernel, cudaFuncAttributeMaxDynamicSharedMemorySize, OUT_SMEM);

    proj_kernel<<<dim3(NTOK/32, 3), 256>>>(Q, K, V, Wq, Wk, Wv, bq, bk, bv);
    transpose_v_kernel<<<dim3(LL/128, BB*NH), 256>>>();
    attn_kernel<<<dim3(LL/QT, BB*NH), 512, ATT_SMEM>>>(mask, attn);
    attn_scale_kernel<<<(int)(ATTN_ELEMS/4/256), 256>>>(attn);
    outproj_kernel<<<NTOK/8, 256, OUT_SMEM>>>(Q, Wo, bo, lng, lnb, out);
    copy_res_kernel<<<OUT_ELEMS/4/256, 256>>>(Q, res);
}